// round 17
// baseline (speedup 1.0000x reference)
#include <cuda_runtime.h>
#include <cstdint>

// 3x3 conv, stride 1, pad 1, single channel, X: (32, 1024, 1024) fp32.
// Two-stage pipelined bulk read (R16) in the 8192-block shape (R12/R14):
// each CTA computes a 4-row x 1024-col band.
//   chunk A: input rows r0-1..r0+2 (16KB) -> bufA (mbarA)
//   chunk B: input rows r0+3..r0+4 ( 8KB) -> bufB (mbarB)
// Copies issued back-to-back; outputs r0,r0+1 computed from bufA while B
// streams in; wait B only before output r0+2. smem 24.2KB -> 7 CTAs/SM
// (~87% occ). One-touch rolling 3-row register window; __stcs stores.
// 8192 one-shot CTAs (minimal replay-to-replay gap).

#define IMG_W 1024
#define IMG_H 1024
#define ROWS_CTA 4
#define A_ROWS 4               // input rows r0-1 .. r0+2
#define B_ROWS 2               // input rows r0+3 .. r0+4

__device__ __forceinline__ uint32_t smem_u32(const void* p) {
    uint32_t a;
    asm("{ .reg .u64 t; cvta.to.shared.u64 t, %1; cvt.u32.u64 %0, t; }"
        : "=r"(a) : "l"(p));
    return a;
}

__global__ __launch_bounds__(256, 7) void conv3x3_kernel(
    const float* __restrict__ X,
    const float* __restrict__ Wt,
    float* __restrict__ Y)
{
    __shared__ __align__(128) float bufA[A_ROWS * IMG_W];   // 16 KB
    __shared__ __align__(128) float bufB[B_ROWS * IMG_W];   //  8 KB
    __shared__ __align__(8)  unsigned long long mbar[2];

    const int tid   = threadIdx.x;
    const int bx    = blockIdx.x;
    const int batch = bx >> 8;            // / 256 bands
    const int band  = bx & 255;
    const int r0    = band << 2;          // first output row
    const int c0    = tid << 2;           // 4 cols per thread (covers 1024)

    const size_t plane = (size_t)IMG_W * IMG_H;
    const float* Xb = X + (size_t)batch * plane;
    float*       Yb = Y + (size_t)batch * plane;

    const uint32_t mbarA = smem_u32(&mbar[0]);
    const uint32_t mbarB = smem_u32(&mbar[1]);
    const uint32_t a_a   = smem_u32(bufA);
    const uint32_t b_a   = smem_u32(bufB);

    if (tid == 0) {
        asm volatile("mbarrier.init.shared.b64 [%0], 1;" :: "r"(mbarA) : "memory");
        asm volatile("mbarrier.init.shared.b64 [%0], 1;" :: "r"(mbarB) : "memory");
    }
    __syncthreads();

    // Chunk A: rows max(r0-1,0) .. r0+2  (r0+2 <= 1022, always valid).
    const int aStart = (r0 - 1 < 0) ? 0 : (r0 - 1);
    const uint32_t aBytes = (uint32_t)(r0 + 2 - aStart + 1) * IMG_W * 4u;
    const uint32_t aDst   = a_a + (uint32_t)(aStart - (r0 - 1)) * IMG_W * 4u;
    // Chunk B: rows r0+3 .. min(r0+4, 1023).
    const int bEnd = (r0 + 4 > IMG_H - 1) ? (IMG_H - 1) : (r0 + 4);
    const uint32_t bBytes = (uint32_t)(bEnd - (r0 + 3) + 1) * IMG_W * 4u;

    if (tid == 0) {
        asm volatile("mbarrier.arrive.expect_tx.shared.b64 _, [%0], %1;"
                     :: "r"(mbarA), "r"(aBytes) : "memory");
        asm volatile(
            "cp.async.bulk.shared::cta.global.mbarrier::complete_tx::bytes "
            "[%0], [%1], %2, [%3];"
            :: "r"(aDst), "l"(Xb + (size_t)aStart * IMG_W), "r"(aBytes),
               "r"(mbarA) : "memory");
        asm volatile("mbarrier.arrive.expect_tx.shared.b64 _, [%0], %1;"
                     :: "r"(mbarB), "r"(bBytes) : "memory");
        asm volatile(
            "cp.async.bulk.shared::cta.global.mbarrier::complete_tx::bytes "
            "[%0], [%1], %2, [%3];"
            :: "r"(b_a), "l"(Xb + (size_t)(r0 + 3) * IMG_W), "r"(bBytes),
               "r"(mbarB) : "memory");
    }

    // Zero pad slots the copies never write (while copies are in flight).
    if (r0 == 0) {
        float4 z = make_float4(0.f, 0.f, 0.f, 0.f);
        *reinterpret_cast<float4*>(&bufA[c0]) = z;           // input row -1
    }
    if (r0 + 4 > IMG_H - 1) {
        float4 z = make_float4(0.f, 0.f, 0.f, 0.f);
        *reinterpret_cast<float4*>(&bufB[(B_ROWS - 1) * IMG_W + c0]) = z; // row 1024
    }

    float w[9];
#pragma unroll
    for (int i = 0; i < 9; i++) w[i] = __ldg(Wt + i);

    // Wait for chunk A; sync makes pad zeros visible across the CTA.
    asm volatile(
        "{\n\t"
        ".reg .pred P;\n\t"
        "WA_%=:\n\t"
        "mbarrier.try_wait.parity.acquire.cta.shared::cta.b64 P, [%0], 0;\n\t"
        "@!P bra WA_%=;\n\t"
        "}"
        :: "r"(mbarA) : "memory");
    __syncthreads();

    // Combined stream: input row (r0-1+k) lives in bufA[k] (k<4) / bufB[k-4].
    float b3[3][6];

#define LOAD_K(dstbuf, k)                                                     \
    do {                                                                      \
        const float* rp = ((k) < A_ROWS) ? &bufA[(k) * IMG_W]                 \
                                         : &bufB[((k) - A_ROWS) * IMG_W];     \
        const float4 v = *reinterpret_cast<const float4*>(rp + c0);           \
        (dstbuf)[1] = v.x; (dstbuf)[2] = v.y;                                 \
        (dstbuf)[3] = v.z; (dstbuf)[4] = v.w;                                 \
        (dstbuf)[0] = (c0 > 0)           ? rp[c0 - 1] : 0.0f;                 \
        (dstbuf)[5] = (c0 + 4 < IMG_W)   ? rp[c0 + 4] : 0.0f;                 \
    } while (0)

    LOAD_K(b3[0], 0);
    LOAD_K(b3[1], 1);

#pragma unroll
    for (int i = 0; i < ROWS_CTA; i++) {
        if (i == 2) {
            // Next row load (k=4) is the first from bufB: wait for chunk B.
            asm volatile(
                "{\n\t"
                ".reg .pred P;\n\t"
                "WB_%=:\n\t"
                "mbarrier.try_wait.parity.acquire.cta.shared::cta.b64 P, [%0], 0;\n\t"
                "@!P bra WB_%=;\n\t"
                "}"
                :: "r"(mbarB) : "memory");
        }
        LOAD_K(b3[(i + 2) % 3], i + 2);

        const float* t0 = b3[i % 3];         // input row r0+i-1  (ky=0)
        const float* t1 = b3[(i + 1) % 3];   // input row r0+i    (ky=1)
        const float* t2 = b3[(i + 2) % 3];   // input row r0+i+1  (ky=2)

        float acc[4];
#pragma unroll
        for (int j = 0; j < 4; j++) {
            float a;
            a = fmaf(w[0], t0[j], fmaf(w[1], t0[j + 1], w[2] * t0[j + 2]));
            a = fmaf(w[3], t1[j], fmaf(w[4], t1[j + 1], fmaf(w[5], t1[j + 2], a)));
            a = fmaf(w[6], t2[j], fmaf(w[7], t2[j + 1], fmaf(w[8], t2[j + 2], a)));
            acc[j] = a;
        }
        float4 o;
        o.x = acc[0]; o.y = acc[1]; o.z = acc[2]; o.w = acc[3];
        __stcs(reinterpret_cast<float4*>(Yb + (size_t)(r0 + i) * IMG_W + c0), o);
    }
#undef LOAD_K
}

extern "C" void kernel_launch(void* const* d_in, const int* in_sizes, int n_in,
                              void* d_out, int out_size)
{
    const float* X  = (const float*)d_in[0];   // (32, 1024, 1024) fp32
    const float* Wt = (const float*)d_in[1];   // (3, 3) fp32
    float* Y        = (float*)d_out;           // (32, 1024, 1024) fp32

    const int grid = 32 * 256;                 // batches * 4-row bands
    conv3x3_kernel<<<grid, 256>>>(X, Wt, Y);
}